// round 5
// baseline (speedup 1.0000x reference)
#include <cuda_runtime.h>
#include <cuda_bf16.h>

#define BB 64      // batch
#define TT 256     // time steps
#define FF 64      // feature
#define UU 512     // units
#define GG 2048    // 4*U
#define K0 576
#define K1 1024

#define NCTA 128
#define NTHR 256
#define UPC 4       // u-columns per CTA
#define NCOL 16     // gate-columns per CTA
#define SK0 580     // ws0 row stride (f4-aligned, ≡4 mod 32)
#define SK1 1028    // ws1 row stride (≡4 mod 32)
#define SHS 68      // h row stride (≡4 mod 32)
#define GES 68      // gacc row stride
#define KSN 8       // split-K slices

__device__ float g_h0[2][BB * UU];
__device__ float g_h1[2][BB * UU];
__device__ float g_dech1[BB * TT * UU];
__device__ unsigned int g_barrier = 0;

__device__ __forceinline__ float sigm(float x) { return 1.0f / (1.0f + __expf(-x)); }

__device__ __forceinline__ void grid_sync() {
    __syncthreads();
    if (threadIdx.x == 0) {
        __threadfence();
        unsigned int me = atomicAdd(&g_barrier, 1u) + 1u;
        unsigned int target = ((me + (NCTA - 1u)) / NCTA) * NCTA;
        while ((int)(*(volatile unsigned int*)&g_barrier - target) < 0) {
            __nanosleep(32);
        }
        __threadfence();
    }
    __syncthreads();
}

// packed f32x2 FMA (Blackwell FFMA2)
__device__ __forceinline__ void ffma2(unsigned long long &acc, unsigned long long a, unsigned long long b) {
    asm("fma.rn.f32x2 %0, %1, %2, %0;" : "+l"(acc) : "l"(a), "l"(b));
}
__device__ __forceinline__ float unpack_sum(unsigned long long v) {
    union { unsigned long long u; float2 f; } cv; cv.u = v;
    return cv.f.x + cv.f.y;
}

#define SMEM_FLOATS (NCOL*SK0 + NCOL*SK1 + 2*64*SHS + KSN*NCOL*GES + 2*UPC*BB + 32)
#define SMEM_BYTES  (SMEM_FLOATS * 4)

// one 64-k chunk of FMAs: 8 cols x 4 rows x 8 k per thread (2 its of 4k)
template<int SK>
__device__ __forceinline__ void chunk_fma(const float* S, const float* WJ,
                                          int cgrp, int rgrp, int ks,
                                          unsigned long long (&acc)[8][4])
{
    #pragma unroll
    for (int it = 0; it < 2; ++it) {
        const int kin = ks * 8 + it * 4;
        ulonglong2 w[8];
        #pragma unroll
        for (int ci = 0; ci < 8; ++ci)
            w[ci] = *(const ulonglong2*)(WJ + (cgrp + 2 * ci) * SK + kin);
        ulonglong2 h[4];
        #pragma unroll
        for (int ri = 0; ri < 4; ++ri)
            h[ri] = *(const ulonglong2*)(S + (rgrp + 16 * ri) * SHS + kin);
        #pragma unroll
        for (int ci = 0; ci < 8; ++ci) {
            #pragma unroll
            for (int ri = 0; ri < 4; ++ri) {
                ffma2(acc[ci][ri], w[ci].x, h[ri].x);
                ffma2(acc[ci][ri], w[ci].y, h[ri].y);
            }
        }
    }
}

__device__ __forceinline__ void store_partials(float* gacc, int cgrp, int rgrp, int ks,
                                               unsigned long long (&acc)[8][4])
{
    #pragma unroll
    for (int ci = 0; ci < 8; ++ci) {
        #pragma unroll
        for (int ri = 0; ri < 4; ++ri)
            gacc[(ks * NCOL + cgrp + 2 * ci) * GES + rgrp + 16 * ri] = unpack_sum(acc[ci][ri]);
    }
}

__global__ void __launch_bounds__(NTHR, 1)
lstm_persistent(const float* __restrict__ inputs,
                const float* __restrict__ targets,
                const float* __restrict__ eW0, const float* __restrict__ eb0,
                const float* __restrict__ eW1, const float* __restrict__ eb1,
                const float* __restrict__ dW0, const float* __restrict__ db0,
                const float* __restrict__ dW1, const float* __restrict__ db1)
{
    extern __shared__ float smem[];
    float* ws0   = smem;
    float* ws1   = ws0 + NCOL * SK0;
    float* shA   = ws1 + NCOL * SK1;
    float* shB   = shA + 64 * SHS;
    float* gacc  = shB + 64 * SHS;            // [KSN][NCOL][GES]
    float* sc    = gacc + KSN * NCOL * GES;   // [layer][ul][b]
    float* sbias = sc + 2 * UPC * BB;         // [0..15]=l0, [16..31]=l1

    const int tid = threadIdx.x;
    const int cta = blockIdx.x;
    const int u0  = cta * UPC;

    // compute mapping: cols cgrp+2*ci (ci 0..7), rows rgrp+16*ri (ri 0..3), k-slice ks
    const int ks   = tid & 7;
    const int cgrp = (tid >> 3) & 1;
    const int rgrp = tid >> 4;          // 0..15

    // staging mapping
    const int prow = tid >> 4;
    const int pq   = (tid & 15) << 2;

    // update mapping
    const int ub  = tid & 63;
    const int uul = tid >> 6;

    // zero initial states: h0 parity-1 and h1 parity-0 are the first-read buffers
    {
        int i = cta * NTHR + tid;   // covers BB*UU
        g_h0[1][i] = 0.0f;
        g_h1[0][i] = 0.0f;
    }
    for (int i = tid; i < 2 * UPC * BB; i += NTHR) sc[i] = 0.0f;
    grid_sync();

    for (int pass = 0; pass < 2; ++pass) {
        const float* W0 = pass ? dW0 : eW0;
        const float* b0 = pass ? db0 : eb0;
        const float* W1 = pass ? dW1 : eW1;
        const float* b1 = pass ? db1 : eb1;
        const float* xs = pass ? targets : inputs;

        // stage weight slice (once per pass)
        {
            int cc = tid & 15;
            int gcol = (cc >> 2) * UU + u0 + (cc & 3);
            for (int k = tid >> 4; k < K0; k += 16) ws0[cc * SK0 + k] = W0[k * GG + gcol];
            for (int k = tid >> 4; k < K1; k += 16) ws1[cc * SK1 + k] = W1[k * GG + gcol];
            if (tid < 16) {
                sbias[tid] = b0[(tid >> 2) * UU + u0 + (tid & 3)];
            } else if (tid < 32) {
                int c2 = tid - 16;
                sbias[tid] = b1[(c2 >> 2) * UU + u0 + (c2 & 3)];
            }
        }
        __syncthreads();

        // merged pipeline: phase p computes layer1(t=p-1) and layer0(t=p).
        // both read parity hold=(p+1)&1 state, write parity hnew=p&1.
        for (int p = 0; p <= TT; ++p) {
            const int hnew = p & 1, hold = hnew ^ 1;
            const float* hr0_old = g_h0[hold];
            const float* hr1_old = g_h1[hold];

            float4 pre[4];

            // ---------------- LAYER 1, t = p-1 (skip at p==0) ----------------
            if (p >= 1) {
                unsigned long long acc[8][4];
                #pragma unroll
                for (int ci = 0; ci < 8; ++ci)
                    #pragma unroll
                    for (int ri = 0; ri < 4; ++ri) acc[ci][ri] = 0ull;

                #pragma unroll
                for (int j = 0; j < 4; ++j)
                    pre[j] = __ldcg((const float4*)(hr0_old + (prow + 16*j) * UU + pq));
                #pragma unroll
                for (int j = 0; j < 4; ++j)
                    *(float4*)(shA + (prow + 16*j) * SHS + pq) = pre[j];
                #pragma unroll
                for (int j = 0; j < 4; ++j)
                    pre[j] = __ldcg((const float4*)(hr0_old + (prow + 16*j) * UU + 64 + pq));

                #pragma unroll 1
                for (int ch = 0; ch < 16; ++ch) {
                    __syncthreads();
                    if (ch + 1 < 16) {
                        float* dst = ((ch + 1) & 1) ? shB : shA;
                        #pragma unroll
                        for (int j = 0; j < 4; ++j)
                            *(float4*)(dst + (prow + 16*j) * SHS + pq) = pre[j];
                        if (ch + 2 < 16) {
                            const int chn = ch + 2;
                            const float* src = (chn < 8) ? (hr0_old + chn * 64)
                                                         : (hr1_old + (chn - 8) * 64);
                            #pragma unroll
                            for (int j = 0; j < 4; ++j)
                                pre[j] = __ldcg((const float4*)(src + (prow + 16*j) * UU + pq));
                        }
                    }
                    const float* S = (ch & 1) ? shB : shA;
                    chunk_fma<SK1>(S, ws1 + ch * 64, cgrp, rgrp, ks, acc);
                }
                store_partials(gacc, cgrp, rgrp, ks, acc);
                __syncthreads();
                // reduce + cell update for layer 1
                {
                    float gs[4];
                    #pragma unroll
                    for (int g = 0; g < 4; ++g) {
                        int col = g * 4 + uul;
                        float s = sbias[16 + col];
                        #pragma unroll
                        for (int si = 0; si < KSN; ++si)
                            s += gacc[(si * NCOL + col) * GES + ub];
                        gs[g] = s;
                    }
                    float cold = sc[256 + uul * 64 + ub];
                    float cn = sigm(gs[2] + 1.0f) * cold + sigm(gs[0]) * tanhf(gs[1]);
                    sc[256 + uul * 64 + ub] = cn;
                    float h = sigm(gs[3]) * tanhf(cn);
                    __stcg(&g_h1[hnew][ub * UU + u0 + uul], h);
                    if (pass == 1) {
                        g_dech1[(ub * TT + (p - 1)) * UU + u0 + uul] = h;
                    }
                }
            }

            // ---------------- LAYER 0, t = p (skip at p==TT) ----------------
            if (p < TT) {
                const float* xbase = xs + p * FF;
                unsigned long long acc[8][4];
                #pragma unroll
                for (int ci = 0; ci < 8; ++ci)
                    #pragma unroll
                    for (int ri = 0; ri < 4; ++ri) acc[ci][ri] = 0ull;

                #pragma unroll
                for (int j = 0; j < 4; ++j)
                    pre[j] = __ldg((const float4*)(xbase + (prow + 16*j) * (TT*FF) + pq));
                __syncthreads();   // ensure prior-phase sh readers done before overwrite
                #pragma unroll
                for (int j = 0; j < 4; ++j)
                    *(float4*)(shA + (prow + 16*j) * SHS + pq) = pre[j];
                #pragma unroll
                for (int j = 0; j < 4; ++j)
                    pre[j] = __ldcg((const float4*)(hr0_old + (prow + 16*j) * UU + pq));

                #pragma unroll 1
                for (int ch = 0; ch < 9; ++ch) {
                    __syncthreads();
                    if (ch + 1 < 9) {
                        float* dst = ((ch + 1) & 1) ? shB : shA;
                        #pragma unroll
                        for (int j = 0; j < 4; ++j)
                            *(float4*)(dst + (prow + 16*j) * SHS + pq) = pre[j];
                        if (ch + 2 < 9) {
                            const float* src = hr0_old + (ch + 1) * 64;
                            #pragma unroll
                            for (int j = 0; j < 4; ++j)
                                pre[j] = __ldcg((const float4*)(src + (prow + 16*j) * UU + pq));
                        }
                    }
                    const float* S = (ch & 1) ? shB : shA;
                    chunk_fma<SK0>(S, ws0 + ch * 64, cgrp, rgrp, ks, acc);
                }
                store_partials(gacc, cgrp, rgrp, ks, acc);
                __syncthreads();
                // reduce + cell update for layer 0
                {
                    float gs[4];
                    #pragma unroll
                    for (int g = 0; g < 4; ++g) {
                        int col = g * 4 + uul;
                        float s = sbias[col];
                        #pragma unroll
                        for (int si = 0; si < KSN; ++si)
                            s += gacc[(si * NCOL + col) * GES + ub];
                        gs[g] = s;
                    }
                    float cold = sc[uul * 64 + ub];
                    float cn = sigm(gs[2] + 1.0f) * cold + sigm(gs[0]) * tanhf(gs[1]);
                    sc[uul * 64 + ub] = cn;
                    float h = sigm(gs[3]) * tanhf(cn);
                    __stcg(&g_h0[hnew][ub * UU + u0 + uul], h);
                }
            }
            grid_sync();
        }
    }
}

// Final projection + length mask
__global__ void proj_kernel(const float* __restrict__ outW,
                            const float* __restrict__ outb,
                            const int* __restrict__ lens,
                            float* __restrict__ out)
{
    __shared__ float shh[UU];
    int bt = blockIdx.x;
    int b  = bt >> 8;
    int t  = bt & 255;
    int f  = threadIdx.x;

    #pragma unroll
    for (int k = f; k < UU; k += 64) shh[k] = g_dech1[bt * UU + k];
    __syncthreads();

    int len = lens[b];
    float val = 0.0f;
    if (t < len) {
        float acc = outb[f];
        #pragma unroll 8
        for (int k = 0; k < UU; ++k) {
            acc += shh[k] * __ldg(&outW[k * FF + f]);
        }
        val = acc;
    }
    out[bt * FF + f] = val;
}

extern "C" void kernel_launch(void* const* d_in, const int* in_sizes, int n_in,
                              void* d_out, int out_size)
{
    const float* inputs  = (const float*)d_in[0];
    const float* targets = (const float*)d_in[1];
    const int*   lens    = (const int*)d_in[2];
    const float* eW0     = (const float*)d_in[3];
    const float* eb0     = (const float*)d_in[4];
    const float* eW1     = (const float*)d_in[5];
    const float* eb1     = (const float*)d_in[6];
    const float* dW0     = (const float*)d_in[7];
    const float* db0     = (const float*)d_in[8];
    const float* dW1     = (const float*)d_in[9];
    const float* db1     = (const float*)d_in[10];
    const float* outW    = (const float*)d_in[11];
    const float* outb    = (const float*)d_in[12];
    float* out = (float*)d_out;

    cudaFuncSetAttribute(lstm_persistent,
                         cudaFuncAttributeMaxDynamicSharedMemorySize, SMEM_BYTES);

    lstm_persistent<<<NCTA, NTHR, SMEM_BYTES>>>(
        inputs, targets, eW0, eb0, eW1, eb1, dW0, db0, dW1, db1);

    proj_kernel<<<BB * TT, 64>>>(outW, outb, lens, out);
}